// round 2
// baseline (speedup 1.0000x reference)
#include <cuda_runtime.h>
#include <cuda_fp16.h>
#include <cstdint>
#include <math.h>

#define Nn 8192
#define NH 64
#define NC 8
#define MAXE (Nn * 32)

// ------------------------- device scratch (static, no allocs) ----------------
__device__ float g_S1[Nn * NH];
__device__ float g_H1[Nn * NH];
__device__ float g_S2[Nn * NH];
__device__ float g_H2[Nn * NH];
__device__ float g_S3[Nn * NC];
__device__ float g_H3[Nn * NC];
__device__ __half g_W1T_hi[NH * Nn];
__device__ __half g_W1T_lo[NH * Nn];
__device__ __half g_W2T_hi[NH * NH];
__device__ __half g_W2T_lo[NH * NH];
__device__ int   g_cnt[Nn];
__device__ int   g_off[Nn];
__device__ int   g_rowptr[Nn + 1];
__device__ int   g_cols[MAXE];
__device__ float g_vals[MAXE];

#define LD32(p) (*reinterpret_cast<const uint32_t*>(p))

// ------------------------- HMMA helper --------------------------------------
__device__ __forceinline__ void mma16816(float c[4], const uint32_t a[4],
                                         uint32_t b0, uint32_t b1) {
    asm volatile(
        "mma.sync.aligned.m16n8k16.row.col.f32.f16.f16.f32 "
        "{%0,%1,%2,%3}, {%4,%5,%6,%7}, {%8,%9}, {%0,%1,%2,%3};"
        : "+f"(c[0]), "+f"(c[1]), "+f"(c[2]), "+f"(c[3])
        : "r"(a[0]), "r"(a[1]), "r"(a[2]), "r"(a[3]), "r"(b0), "r"(b1));
}

// ------------------------- weight transpose + fp16 hi/lo split ---------------
__global__ void prep_wt_kernel(const float* __restrict__ W, int Kdim, int which) {
    int idx = blockIdx.x * blockDim.x + threadIdx.x;
    int total = NH * Kdim;
    if (idx >= total) return;
    int n = idx / Kdim;
    int k = idx - n * Kdim;
    float w = W[(size_t)k * NH + n];
    __half h = __float2half_rn(w);
    __half l = __float2half_rn(w - __half2float(h));
    if (which == 0) { g_W1T_hi[idx] = h; g_W1T_lo[idx] = l; }
    else            { g_W2T_hi[idx] = h; g_W2T_lo[idx] = l; }
}

// ------------------------- CSR build ----------------------------------------
__global__ void zero_cnt_kernel() {
    int i = blockIdx.x * blockDim.x + threadIdx.x;
    if (i < Nn) { g_cnt[i] = 0; g_off[i] = 0; }
}

__global__ void hist_kernel(const int* __restrict__ row, int E) {
    int e = blockIdx.x * blockDim.x + threadIdx.x;
    if (e < E) atomicAdd(&g_cnt[row[e]], 1);
}

__global__ void scan_kernel() {
    __shared__ int sums[256];
    int t = threadIdx.x;
    int base = t * 32;
    int s = 0;
    #pragma unroll
    for (int i = 0; i < 32; i++) s += g_cnt[base + i];
    sums[t] = s;
    __syncthreads();
    if (t == 0) {
        int acc = 0;
        for (int i = 0; i < 256; i++) { int v = sums[i]; sums[i] = acc; acc += v; }
        g_rowptr[Nn] = acc;
    }
    __syncthreads();
    int acc = sums[t];
    for (int i = 0; i < 32; i++) { g_rowptr[base + i] = acc; acc += g_cnt[base + i]; }
}

__global__ void scatter_kernel(const int* __restrict__ row, const int* __restrict__ col,
                               const float* __restrict__ val, int E) {
    int e = blockIdx.x * blockDim.x + threadIdx.x;
    if (e < E) {
        int r = row[e];
        int p = g_rowptr[r] + atomicAdd(&g_off[r], 1);
        g_cols[p] = col[e];
        g_vals[p] = val[e];
    }
}

// ------------------------- HMMA split-fp16 GEMM ------------------------------
// C[8192 x 64] = A[8192 x Kdim] @ W[Kdim x 64]
// MODE 0 (layer1): A = x (fp32 ext) -> fp16 on the fly (single), W hi/lo split,
//                  2 products: a_h*w_h + a_h*w_l.
// MODE 1 (layer2): A = g_H1 hi/lo split, W hi/lo split,
//                  3 products: a_h*w_h + a_h*w_l + a_l*w_h.
// Block: 128 threads (4 warps, 2x2 warp grid), tile 64(m) x 64(n).
// smem per buffer: A_hi [64x72h], A_lo, B_hi, B_lo  (9216 B each, padded stride
// 72 halves = conflict-free 32-bit LDS fragments). Double buffered: 73728 B.
#define BUF_BYTES 36864
#define GT_SMEM   (2 * BUF_BYTES)

template <int MODE>
__device__ __forceinline__ void compute_chunk(const char* base, int lane, int wm, int wn,
                                              float acc[2][4][4]) {
    const int g = lane >> 2, tg = lane & 3;
    const __half* Ah = (const __half*)(base);
    const __half* Al = (const __half*)(base + 9216);
    const __half* Bh = (const __half*)(base + 18432);
    const __half* Bl = (const __half*)(base + 27648);
    #pragma unroll
    for (int ks = 0; ks < 4; ks++) {
        uint32_t ah[2][4], al[2][4];
        #pragma unroll
        for (int mt = 0; mt < 2; mt++) {
            const __half* p = Ah + (wm + mt * 16 + g) * 72 + ks * 16 + 2 * tg;
            ah[mt][0] = LD32(p);
            ah[mt][1] = LD32(p + 8 * 72);
            ah[mt][2] = LD32(p + 8);
            ah[mt][3] = LD32(p + 8 * 72 + 8);
            if (MODE == 1) {
                const __half* q = Al + (wm + mt * 16 + g) * 72 + ks * 16 + 2 * tg;
                al[mt][0] = LD32(q);
                al[mt][1] = LD32(q + 8 * 72);
                al[mt][2] = LD32(q + 8);
                al[mt][3] = LD32(q + 8 * 72 + 8);
            }
        }
        #pragma unroll
        for (int nt = 0; nt < 4; nt++) {
            const __half* q  = Bh + (wn + nt * 8 + g) * 72 + ks * 16 + 2 * tg;
            const __half* ql = Bl + (wn + nt * 8 + g) * 72 + ks * 16 + 2 * tg;
            uint32_t b0 = LD32(q),  b1 = LD32(q + 8);
            uint32_t c0 = LD32(ql), c1 = LD32(ql + 8);
            #pragma unroll
            for (int mt = 0; mt < 2; mt++) {
                mma16816(acc[mt][nt], ah[mt], b0, b1);
                mma16816(acc[mt][nt], ah[mt], c0, c1);
                if (MODE == 1) mma16816(acc[mt][nt], al[mt], b0, b1);
            }
        }
    }
}

template <int MODE>
__global__ void __launch_bounds__(128, 1)
gemm_hmma(const float* __restrict__ Aext, int Kdim) {
    extern __shared__ char smem[];
    const int tid = threadIdx.x, lane = tid & 31, w = tid >> 5;
    const int m0 = blockIdx.x * 64;
    const float* A = (MODE == 0) ? Aext : g_H1;
    const __half* BTh = (MODE == 0) ? g_W1T_hi : g_W2T_hi;
    const __half* BTl = (MODE == 0) ? g_W1T_lo : g_W2T_lo;
    float* C = (MODE == 0) ? g_S1 : g_S2;
    const int wm = (w & 1) * 32, wn = (w >> 1) * 32;

    float acc[2][4][4];
    #pragma unroll
    for (int mt = 0; mt < 2; mt++)
        #pragma unroll
        for (int nt = 0; nt < 4; nt++)
            #pragma unroll
            for (int q = 0; q < 4; q++) acc[mt][nt][q] = 0.f;

    float4 pa[8];
    uint4 pbh[4], pbl[4];
    const int nch = Kdim >> 6;

    auto loadc = [&](int kc) {
        const float* Ab = A + (size_t)m0 * Kdim + (size_t)kc * 64;
        #pragma unroll
        for (int i = 0; i < 8; i++) {
            int j = tid + i * 128, r = j >> 4, c = j & 15;
            pa[i] = *(const float4*)(Ab + (size_t)r * Kdim + c * 4);
        }
        const __half* Bb_h = BTh + (size_t)kc * 64;
        const __half* Bb_l = BTl + (size_t)kc * 64;
        #pragma unroll
        for (int i = 0; i < 4; i++) {
            int j = tid + i * 128, r = j >> 3, c = j & 7;
            pbh[i] = *(const uint4*)(Bb_h + (size_t)r * Kdim + c * 8);
            pbl[i] = *(const uint4*)(Bb_l + (size_t)r * Kdim + c * 8);
        }
    };
    auto storec = [&](int buf) {
        char* base = smem + buf * BUF_BYTES;
        #pragma unroll
        for (int i = 0; i < 8; i++) {
            int j = tid + i * 128, r = j >> 4, c = j & 15;
            __half2 h01 = __floats2half2_rn(pa[i].x, pa[i].y);
            __half2 h23 = __floats2half2_rn(pa[i].z, pa[i].w);
            uint2 u;
            u.x = *reinterpret_cast<uint32_t*>(&h01);
            u.y = *reinterpret_cast<uint32_t*>(&h23);
            *reinterpret_cast<uint2*>(base + r * 144 + c * 8) = u;
            if (MODE == 1) {
                __half2 l01 = __floats2half2_rn(pa[i].x - __low2float(h01),
                                                pa[i].y - __high2float(h01));
                __half2 l23 = __floats2half2_rn(pa[i].z - __low2float(h23),
                                                pa[i].w - __high2float(h23));
                uint2 v;
                v.x = *reinterpret_cast<uint32_t*>(&l01);
                v.y = *reinterpret_cast<uint32_t*>(&l23);
                *reinterpret_cast<uint2*>(base + 9216 + r * 144 + c * 8) = v;
            }
        }
        #pragma unroll
        for (int i = 0; i < 4; i++) {
            int j = tid + i * 128, r = j >> 3, c = j & 7;
            *reinterpret_cast<uint4*>(base + 18432 + r * 144 + c * 16) = pbh[i];
            *reinterpret_cast<uint4*>(base + 27648 + r * 144 + c * 16) = pbl[i];
        }
    };

    loadc(0);
    storec(0);
    __syncthreads();
    for (int kc = 0; kc < nch; kc++) {
        if (kc + 1 < nch) loadc(kc + 1);
        compute_chunk<MODE>(smem + (kc & 1) * BUF_BYTES, lane, wm, wn, acc);
        if (kc + 1 < nch) {
            storec((kc + 1) & 1);
            __syncthreads();
        }
    }

    const int g = lane >> 2, tg = lane & 3;
    #pragma unroll
    for (int mt = 0; mt < 2; mt++)
        #pragma unroll
        for (int nt = 0; nt < 4; nt++) {
            int row = m0 + wm + mt * 16 + g;
            int col = wn + nt * 8 + 2 * tg;
            *reinterpret_cast<float2*>(&C[(size_t)row * 64 + col]) =
                make_float2(acc[mt][nt][0], acc[mt][nt][1]);
            *reinterpret_cast<float2*>(&C[(size_t)(row + 8) * 64 + col]) =
                make_float2(acc[mt][nt][2], acc[mt][nt][3]);
        }
}

// ------------------------- SpMM (warp per row) + bias + relu -----------------
__global__ void spmm64_kernel(const float* __restrict__ bias, int which) {
    int gt = blockIdx.x * blockDim.x + threadIdx.x;
    int row = gt >> 5, lane = gt & 31;
    if (row >= Nn) return;
    const float* S = (which == 0) ? g_S1 : g_S2;
    float* H = (which == 0) ? g_H1 : g_H2;
    int s = g_rowptr[row], e = g_rowptr[row + 1];
    float a0 = 0.f, a1 = 0.f;
    for (int i = s; i < e; i++) {
        int c = g_cols[i];
        float v = g_vals[i];
        const float* Sr = S + (size_t)c * 64;
        a0 += v * Sr[lane];
        a1 += v * Sr[lane + 32];
    }
    float r0 = a0 + bias[lane];
    float r1 = a1 + bias[lane + 32];
    H[(size_t)row * 64 + lane]      = fmaxf(r0, 0.f);
    H[(size_t)row * 64 + lane + 32] = fmaxf(r1, 0.f);
}

// ------------------------- layer 3 dense (tiny, fp32) ------------------------
__global__ void gemm3_kernel(const float* __restrict__ W3) {
    __shared__ float w[64 * 8];
    int t = threadIdx.x;
    for (int i = t; i < 512; i += blockDim.x) w[i] = W3[i];
    __syncthreads();
    int row = blockIdx.x * blockDim.x + t;
    if (row >= Nn) return;
    const float* h = g_H2 + (size_t)row * 64;
    float acc[8];
    #pragma unroll
    for (int f = 0; f < 8; f++) acc[f] = 0.f;
    #pragma unroll 8
    for (int k = 0; k < 64; k++) {
        float x = h[k];
        #pragma unroll
        for (int f = 0; f < 8; f++) acc[f] += x * w[k * 8 + f];
    }
    #pragma unroll
    for (int f = 0; f < 8; f++) g_S3[(size_t)row * 8 + f] = acc[f];
}

__global__ void spmm8_kernel(const float* __restrict__ b3) {
    int row = blockIdx.x * blockDim.x + threadIdx.x;
    if (row >= Nn) return;
    int s = g_rowptr[row], e = g_rowptr[row + 1];
    float a0 = 0.f, a1 = 0.f, a2 = 0.f, a3 = 0.f, a4 = 0.f, a5 = 0.f, a6 = 0.f, a7 = 0.f;
    for (int i = s; i < e; i++) {
        int c = g_cols[i];
        float v = g_vals[i];
        const float4* p = reinterpret_cast<const float4*>(g_S3 + (size_t)c * 8);
        float4 q0 = p[0], q1 = p[1];
        a0 += v * q0.x; a1 += v * q0.y; a2 += v * q0.z; a3 += v * q0.w;
        a4 += v * q1.x; a5 += v * q1.y; a6 += v * q1.z; a7 += v * q1.w;
    }
    float* o = g_H3 + (size_t)row * 8;
    o[0] = a0 + b3[0]; o[1] = a1 + b3[1]; o[2] = a2 + b3[2]; o[3] = a3 + b3[3];
    o[4] = a4 + b3[4]; o[5] = a5 + b3[5]; o[6] = a6 + b3[6]; o[7] = a7 + b3[7];
}

// ------------------------- log_softmax + final linear -------------------------
__global__ void out_init_kernel(const float* __restrict__ blin, float* __restrict__ out) {
    if (threadIdx.x < 8) out[threadIdx.x] = blin[0];
}

__global__ void final_kernel(const float* __restrict__ Wlin, float* __restrict__ out) {
    __shared__ float red[256 * 8];
    float loc[8];
    #pragma unroll
    for (int f = 0; f < 8; f++) loc[f] = 0.f;
    for (int r = blockIdx.x * blockDim.x + threadIdx.x; r < Nn; r += gridDim.x * blockDim.x) {
        const float4* p = reinterpret_cast<const float4*>(g_H3 + (size_t)r * 8);
        float4 q0 = p[0], q1 = p[1];
        float h[8] = {q0.x, q0.y, q0.z, q0.w, q1.x, q1.y, q1.z, q1.w};
        float m = h[0];
        #pragma unroll
        for (int f = 1; f < 8; f++) m = fmaxf(m, h[f]);
        float ssum = 0.f;
        #pragma unroll
        for (int f = 0; f < 8; f++) ssum += expf(h[f] - m);
        float lse = m + logf(ssum);
        float wv = Wlin[r];
        #pragma unroll
        for (int f = 0; f < 8; f++) loc[f] += (h[f] - lse) * wv;
    }
    int t = threadIdx.x;
    #pragma unroll
    for (int f = 0; f < 8; f++) red[t * 8 + f] = loc[f];
    __syncthreads();
    for (int s2 = 128; s2 > 0; s2 >>= 1) {
        if (t < s2) {
            #pragma unroll
            for (int f = 0; f < 8; f++) red[t * 8 + f] += red[(t + s2) * 8 + f];
        }
        __syncthreads();
    }
    if (t < 8) atomicAdd(&out[t], red[t]);
}

// ------------------------- launch -------------------------------------------
extern "C" void kernel_launch(void* const* d_in, const int* in_sizes, int n_in,
                              void* d_out, int out_size) {
    const float* x    = (const float*)d_in[0];
    const int*   arow = (const int*)d_in[1];
    const int*   acol = (const int*)d_in[2];
    const float* aval = (const float*)d_in[3];
    const float* W1   = (const float*)d_in[4];
    const float* b1   = (const float*)d_in[5];
    const float* W2   = (const float*)d_in[6];
    const float* b2   = (const float*)d_in[7];
    const float* W3   = (const float*)d_in[8];
    const float* b3   = (const float*)d_in[9];
    const float* Wlin = (const float*)d_in[10];
    const float* blin = (const float*)d_in[11];
    const int E = in_sizes[1];
    float* out = (float*)d_out;

    cudaFuncSetAttribute(gemm_hmma<0>, cudaFuncAttributeMaxDynamicSharedMemorySize, GT_SMEM);
    cudaFuncSetAttribute(gemm_hmma<1>, cudaFuncAttributeMaxDynamicSharedMemorySize, GT_SMEM);

    // weight prep (transpose + fp16 hi/lo split)
    prep_wt_kernel<<<(NH * Nn + 255) / 256, 256>>>(W1, Nn, 0);
    prep_wt_kernel<<<(NH * NH + 255) / 256, 256>>>(W2, NH, 1);

    // CSR build from COO (once; reused by all 3 spmm layers)
    zero_cnt_kernel<<<Nn / 256, 256>>>();
    hist_kernel<<<(E + 255) / 256, 256>>>(arow, E);
    scan_kernel<<<1, 256>>>();
    scatter_kernel<<<(E + 255) / 256, 256>>>(arow, acol, aval, E);

    // layer 1
    gemm_hmma<0><<<Nn / 64, 128, GT_SMEM>>>(x, Nn);
    spmm64_kernel<<<(Nn * 32) / 256, 256>>>(b1, 0);
    // layer 2
    gemm_hmma<1><<<Nn / 64, 128, GT_SMEM>>>(nullptr, NH);
    spmm64_kernel<<<(Nn * 32) / 256, 256>>>(b2, 1);
    // layer 3
    gemm3_kernel<<<Nn / 256, 256>>>(W3);
    spmm8_kernel<<<Nn / 256, 256>>>(b3);
    // log_softmax + linear head
    out_init_kernel<<<1, 32>>>(blin, out);
    final_kernel<<<64, 256>>>(Wlin, out);
}

// round 3
// speedup vs baseline: 1.0877x; 1.0877x over previous
#include <cuda_runtime.h>
#include <cuda_fp16.h>
#include <cstdint>
#include <math.h>

#define Nn 8192
#define NH 64
#define NC 8
#define MAXE (Nn * 32)

// ------------------------- device scratch (static, no allocs) ----------------
__device__ float g_S1[Nn * NH];
__device__ float g_H1[Nn * NH];
__device__ float g_S2[Nn * NH];
__device__ float g_S3[Nn * NC];
__device__ __half g_W1T_hi[NH * Nn];
__device__ __half g_W2T_hi[NH * NH];
__device__ __half g_W2T_lo[NH * NH];
__device__ int   g_cnt[Nn];
__device__ int   g_off[Nn];
__device__ int   g_rowptr[Nn + 1];
__device__ int   g_cols[MAXE];
__device__ float g_vals[MAXE];

#define LD32(p) (*reinterpret_cast<const uint32_t*>(p))

// ------------------------- HMMA helper --------------------------------------
__device__ __forceinline__ void mma16816(float c[4], const uint32_t a[4],
                                         uint32_t b0, uint32_t b1) {
    asm volatile(
        "mma.sync.aligned.m16n8k16.row.col.f32.f16.f16.f32 "
        "{%0,%1,%2,%3}, {%4,%5,%6,%7}, {%8,%9}, {%0,%1,%2,%3};"
        : "+f"(c[0]), "+f"(c[1]), "+f"(c[2]), "+f"(c[3])
        : "r"(a[0]), "r"(a[1]), "r"(a[2]), "r"(a[3]), "r"(b0), "r"(b1));
}

__device__ __forceinline__ void cp_async16(void* dst, const void* src) {
    uint32_t d = (uint32_t)__cvta_generic_to_shared(dst);
    asm volatile("cp.async.cg.shared.global [%0], [%1], 16;" :: "r"(d), "l"(src));
}
__device__ __forceinline__ void cp_commit() {
    asm volatile("cp.async.commit_group;");
}
__device__ __forceinline__ void cp_wait_all() {
    asm volatile("cp.async.wait_group 0;");
}

// ------------------------- setup: zero cnt/off, W2 split, out init -----------
__global__ void setup_kernel(const float* __restrict__ W2,
                             const float* __restrict__ blin, float* __restrict__ out) {
    int i = blockIdx.x * blockDim.x + threadIdx.x;
    if (i < Nn) { g_cnt[i] = 0; g_off[i] = 0; }
    if (i < NH * NH) {
        int n = i >> 6, k = i & 63;
        float w = W2[k * NH + n];
        __half h = __float2half_rn(w);
        g_W2T_hi[i] = h;
        g_W2T_lo[i] = __float2half_rn(w - __half2float(h));
    }
    if (i < NC) out[i] = blin[0];
}

// ------------------------- hist (vectorized) ---------------------------------
__global__ void hist_kernel(const int* __restrict__ row, int E) {
    int i = (blockIdx.x * blockDim.x + threadIdx.x) * 4;
    if (i + 3 < E) {
        int4 r = *reinterpret_cast<const int4*>(row + i);
        atomicAdd(&g_cnt[r.x], 1);
        atomicAdd(&g_cnt[r.y], 1);
        atomicAdd(&g_cnt[r.z], 1);
        atomicAdd(&g_cnt[r.w], 1);
    } else {
        for (int j = i; j < E; j++) atomicAdd(&g_cnt[row[j]], 1);
    }
}

// ------------------------- W1 transpose (coalesced, smem tile) ---------------
__global__ void transpose_w1(const float* __restrict__ W1) {
    __shared__ float t[32][65];
    int k0 = blockIdx.x * 32;
    int tid = threadIdx.x;
    #pragma unroll
    for (int i = 0; i < 8; i++) {
        int j = tid + i * 256;          // 2048 = 32 rows x 64 cols
        int r = j >> 6, c = j & 63;
        t[r][c] = W1[(size_t)(k0 + r) * NH + c];
    }
    __syncthreads();
    #pragma unroll
    for (int i = 0; i < 8; i++) {
        int j = tid + i * 256;          // 2048 = 64 n x 32 k
        int c = j >> 5, r = j & 31;
        g_W1T_hi[(size_t)c * Nn + k0 + r] = __float2half_rn(t[r][c]);
    }
}

// ------------------------- shfl-based exclusive scan -------------------------
__global__ void scan_kernel() {
    __shared__ int wsum[8];
    int t = threadIdx.x, lane = t & 31, w = t >> 5;
    int base = t * 32;
    int s = 0;
    #pragma unroll
    for (int i = 0; i < 32; i++) s += g_cnt[base + i];
    int incl = s;
    #pragma unroll
    for (int o = 1; o < 32; o <<= 1) {
        int v = __shfl_up_sync(0xFFFFFFFFu, incl, o);
        if (lane >= o) incl += v;
    }
    if (lane == 31) wsum[w] = incl;
    __syncthreads();
    if (w == 0 && lane < 8) {
        int v = wsum[lane];
        int iw = v;
        #pragma unroll
        for (int o = 1; o < 8; o <<= 1) {
            int u = __shfl_up_sync(0x000000FFu, iw, o);
            if (lane >= o) iw += u;
        }
        wsum[lane] = iw - v;   // exclusive warp offset
    }
    __syncthreads();
    int acc = incl - s + wsum[w];
    #pragma unroll
    for (int i = 0; i < 32; i++) { g_rowptr[base + i] = acc; acc += g_cnt[base + i]; }
    if (t == 255) g_rowptr[Nn] = acc;
}

__global__ void scatter_kernel(const int* __restrict__ row, const int* __restrict__ col,
                               const float* __restrict__ val, int E) {
    int e = blockIdx.x * blockDim.x + threadIdx.x;
    if (e < E) {
        int r = row[e];
        int p = g_rowptr[r] + atomicAdd(&g_off[r], 1);
        g_cols[p] = col[e];
        g_vals[p] = val[e];
    }
}

// ------------------------- HMMA GEMM ------------------------------------------
// C[8192 x 64] = A[8192 x Kdim] @ W[Kdim x 64]
// MODE 0: A = x (fp32) -> fp16 single, B = W1T_hi only  (1 product)
// MODE 1: A = g_H1 hi/lo, B = W2T hi/lo                 (3 products)
// 256 threads, 8 warps in 4(m) x 2(n) grid; block tile 64m x 64n; chunk K=64.
// smem buffer: A_hi [64x72h]=9216B @0, B_hi 9216B @9216,
//              MODE1: A_lo @18432, B_lo @27648. Double buffered.
template <int MODE>
__global__ void __launch_bounds__(256, 1)
gemm_hmma(const float* __restrict__ Aext, int Kdim) {
    constexpr int BH  = 9216;
    constexpr int AL  = 18432;
    constexpr int BL  = 27648;
    constexpr int BUF = MODE ? 36864 : 18432;
    extern __shared__ char smem[];
    const int tid = threadIdx.x, lane = tid & 31, w = tid >> 5;
    const int m0 = blockIdx.x * 64;
    const int wm = (w & 3) * 16, wn = (w >> 2) * 32;
    const int g = lane >> 2, tg = lane & 3;

    const float* A = (MODE == 0) ? Aext : g_H1;
    const __half* BTh = (MODE == 0) ? g_W1T_hi : g_W2T_hi;
    const __half* BTl = (MODE == 0) ? (const __half*)nullptr : g_W2T_lo;
    float* C = (MODE == 0) ? g_S1 : g_S2;

    float acc[4][4];
    #pragma unroll
    for (int nt = 0; nt < 4; nt++)
        #pragma unroll
        for (int q = 0; q < 4; q++) acc[nt][q] = 0.f;

    float4 pa[4];
    const int nch = Kdim >> 6;

    auto cpasyncB = [&](int kc, char* base) {
        #pragma unroll
        for (int i = 0; i < 2; i++) {
            int j = tid + i * 256, r = j >> 3, c = j & 7;
            cp_async16(base + BH + r * 144 + c * 16,
                       BTh + (size_t)r * Kdim + kc * 64 + c * 8);
            if (MODE == 1)
                cp_async16(base + BL + r * 144 + c * 16,
                           BTl + (size_t)r * Kdim + kc * 64 + c * 8);
        }
    };
    auto loadA = [&](int kc) {
        const float* Ab = A + (size_t)m0 * Kdim + (size_t)kc * 64;
        #pragma unroll
        for (int i = 0; i < 4; i++) {
            int j = tid + i * 256, r = j >> 4, c = j & 15;
            pa[i] = *reinterpret_cast<const float4*>(Ab + (size_t)r * Kdim + c * 4);
        }
    };
    auto storeA = [&](char* base) {
        #pragma unroll
        for (int i = 0; i < 4; i++) {
            int j = tid + i * 256, r = j >> 4, c = j & 15;
            __half2 h01 = __floats2half2_rn(pa[i].x, pa[i].y);
            __half2 h23 = __floats2half2_rn(pa[i].z, pa[i].w);
            uint2 u;
            u.x = *reinterpret_cast<uint32_t*>(&h01);
            u.y = *reinterpret_cast<uint32_t*>(&h23);
            *reinterpret_cast<uint2*>(base + r * 144 + c * 8) = u;
            if (MODE == 1) {
                __half2 l01 = __floats2half2_rn(pa[i].x - __low2float(h01),
                                                pa[i].y - __high2float(h01));
                __half2 l23 = __floats2half2_rn(pa[i].z - __low2float(h23),
                                                pa[i].w - __high2float(h23));
                uint2 v;
                v.x = *reinterpret_cast<uint32_t*>(&l01);
                v.y = *reinterpret_cast<uint32_t*>(&l23);
                *reinterpret_cast<uint2*>(base + AL + r * 144 + c * 8) = v;
            }
        }
    };
    auto compute = [&](const char* base) {
        const __half* Ah = (const __half*)(base);
        const __half* Al = (const __half*)(base + AL);
        const __half* Bh = (const __half*)(base + BH);
        const __half* Bl = (const __half*)(base + BL);
        #pragma unroll
        for (int ks = 0; ks < 4; ks++) {
            uint32_t ah[4], al[4];
            const __half* p = Ah + (wm + g) * 72 + ks * 16 + 2 * tg;
            ah[0] = LD32(p);
            ah[1] = LD32(p + 8 * 72);
            ah[2] = LD32(p + 8);
            ah[3] = LD32(p + 8 * 72 + 8);
            if (MODE == 1) {
                const __half* q = Al + (wm + g) * 72 + ks * 16 + 2 * tg;
                al[0] = LD32(q);
                al[1] = LD32(q + 8 * 72);
                al[2] = LD32(q + 8);
                al[3] = LD32(q + 8 * 72 + 8);
            }
            #pragma unroll
            for (int nt = 0; nt < 4; nt++) {
                const __half* q = Bh + (wn + nt * 8 + g) * 72 + ks * 16 + 2 * tg;
                uint32_t b0 = LD32(q), b1 = LD32(q + 8);
                mma16816(acc[nt], ah, b0, b1);
                if (MODE == 1) {
                    const __half* ql = Bl + (wn + nt * 8 + g) * 72 + ks * 16 + 2 * tg;
                    uint32_t c0 = LD32(ql), c1 = LD32(ql + 8);
                    mma16816(acc[nt], ah, c0, c1);
                    mma16816(acc[nt], al, b0, b1);
                }
            }
        }
    };

    // prologue
    cpasyncB(0, smem);
    cp_commit();
    loadA(0);
    storeA(smem);
    cp_wait_all();
    __syncthreads();

    for (int kc = 0; kc < nch; kc++) {
        char* cur = smem + (kc & 1) * BUF;
        char* nxt = smem + ((kc + 1) & 1) * BUF;
        if (kc + 1 < nch) {
            cpasyncB(kc + 1, nxt);
            cp_commit();
            loadA(kc + 1);
        }
        compute(cur);
        if (kc + 1 < nch) {
            storeA(nxt);
            cp_wait_all();
            __syncthreads();
        }
    }

    #pragma unroll
    for (int nt = 0; nt < 4; nt++) {
        int row = m0 + wm + g;
        int col = wn + nt * 8 + 2 * tg;
        *reinterpret_cast<float2*>(&C[(size_t)row * 64 + col]) =
            make_float2(acc[nt][0], acc[nt][1]);
        *reinterpret_cast<float2*>(&C[(size_t)(row + 8) * 64 + col]) =
            make_float2(acc[nt][2], acc[nt][3]);
    }
}

// ------------------------- SpMM layer 1: S1 -> H1 (bias+relu) ---------------
__global__ void spmm64_l1(const float* __restrict__ bias) {
    int gt = blockIdx.x * blockDim.x + threadIdx.x;
    int row = gt >> 5, lane = gt & 31;
    if (row >= Nn) return;
    int s = g_rowptr[row], e = g_rowptr[row + 1];
    float a0 = 0.f, a1 = 0.f;
    #pragma unroll 4
    for (int i = s; i < e; i++) {
        int c = g_cols[i];
        float v = g_vals[i];
        const float* Sr = g_S1 + (size_t)c * 64;
        a0 += v * Sr[lane];
        a1 += v * Sr[lane + 32];
    }
    g_H1[(size_t)row * 64 + lane]      = fmaxf(a0 + bias[lane], 0.f);
    g_H1[(size_t)row * 64 + lane + 32] = fmaxf(a1 + bias[lane + 32], 0.f);
}

// ------------------------- SpMM layer 2 fused with gemm3: S2 -> S3 ----------
__global__ void spmm64_l2(const float* __restrict__ bias, const float* __restrict__ W3) {
    __shared__ float w3[NH * NC];
    int tid = threadIdx.x;
    for (int i = tid; i < NH * NC; i += blockDim.x) w3[i] = W3[i];
    __syncthreads();
    int gt = blockIdx.x * blockDim.x + tid;
    int row = gt >> 5, lane = gt & 31;
    if (row >= Nn) return;
    int s = g_rowptr[row], e = g_rowptr[row + 1];
    float a0 = 0.f, a1 = 0.f;
    #pragma unroll 4
    for (int i = s; i < e; i++) {
        int c = g_cols[i];
        float v = g_vals[i];
        const float* Sr = g_S2 + (size_t)c * 64;
        a0 += v * Sr[lane];
        a1 += v * Sr[lane + 32];
    }
    float r0 = fmaxf(a0 + bias[lane], 0.f);
    float r1 = fmaxf(a1 + bias[lane + 32], 0.f);
    // gemm3: S3[row][f] = sum_k h_k * W3[k][f]
    float p[NC];
    #pragma unroll
    for (int f = 0; f < NC; f++)
        p[f] = r0 * w3[lane * NC + f] + r1 * w3[(lane + 32) * NC + f];
    #pragma unroll
    for (int o = 16; o > 0; o >>= 1)
        #pragma unroll
        for (int f = 0; f < NC; f++) p[f] += __shfl_xor_sync(0xFFFFFFFFu, p[f], o);
    if (lane == 0) {
        float* o8 = g_S3 + (size_t)row * NC;
        *reinterpret_cast<float4*>(o8)     = make_float4(p[0], p[1], p[2], p[3]);
        *reinterpret_cast<float4*>(o8 + 4) = make_float4(p[4], p[5], p[6], p[7]);
    }
}

// ------------------------- final: spmm8 + bias + log_softmax + head ---------
__global__ void final_fused(const float* __restrict__ b3, const float* __restrict__ Wlin,
                            float* __restrict__ out) {
    __shared__ float red[256 * NC];
    int t = threadIdx.x;
    int row = blockIdx.x * blockDim.x + t;
    float h[NC];
    {
        int s = g_rowptr[row], e = g_rowptr[row + 1];
        float a0 = 0.f, a1 = 0.f, a2 = 0.f, a3 = 0.f, a4 = 0.f, a5 = 0.f, a6 = 0.f, a7 = 0.f;
        #pragma unroll 2
        for (int i = s; i < e; i++) {
            int c = g_cols[i];
            float v = g_vals[i];
            const float4* p = reinterpret_cast<const float4*>(g_S3 + (size_t)c * NC);
            float4 q0 = p[0], q1 = p[1];
            a0 += v * q0.x; a1 += v * q0.y; a2 += v * q0.z; a3 += v * q0.w;
            a4 += v * q1.x; a5 += v * q1.y; a6 += v * q1.z; a7 += v * q1.w;
        }
        h[0] = a0 + b3[0]; h[1] = a1 + b3[1]; h[2] = a2 + b3[2]; h[3] = a3 + b3[3];
        h[4] = a4 + b3[4]; h[5] = a5 + b3[5]; h[6] = a6 + b3[6]; h[7] = a7 + b3[7];
    }
    float m = h[0];
    #pragma unroll
    for (int f = 1; f < NC; f++) m = fmaxf(m, h[f]);
    float ssum = 0.f;
    #pragma unroll
    for (int f = 0; f < NC; f++) ssum += expf(h[f] - m);
    float lse = m + logf(ssum);
    float wv = Wlin[row];
    #pragma unroll
    for (int f = 0; f < NC; f++) red[t * NC + f] = (h[f] - lse) * wv;
    __syncthreads();
    for (int s2 = 128; s2 > 0; s2 >>= 1) {
        if (t < s2) {
            #pragma unroll
            for (int f = 0; f < NC; f++) red[t * NC + f] += red[(t + s2) * NC + f];
        }
        __syncthreads();
    }
    if (t < NC) atomicAdd(&out[t], red[t]);
}

// ------------------------- launch -------------------------------------------
extern "C" void kernel_launch(void* const* d_in, const int* in_sizes, int n_in,
                              void* d_out, int out_size) {
    const float* x    = (const float*)d_in[0];
    const int*   arow = (const int*)d_in[1];
    const int*   acol = (const int*)d_in[2];
    const float* aval = (const float*)d_in[3];
    const float* W1   = (const float*)d_in[4];
    const float* b1   = (const float*)d_in[5];
    const float* W2   = (const float*)d_in[6];
    const float* b2   = (const float*)d_in[7];
    const float* W3   = (const float*)d_in[8];
    const float* b3   = (const float*)d_in[9];
    const float* Wlin = (const float*)d_in[10];
    const float* blin = (const float*)d_in[11];
    const int E = in_sizes[1];
    float* out = (float*)d_out;

    cudaFuncSetAttribute(gemm_hmma<0>, cudaFuncAttributeMaxDynamicSharedMemorySize, 2 * 18432);
    cudaFuncSetAttribute(gemm_hmma<1>, cudaFuncAttributeMaxDynamicSharedMemorySize, 2 * 36864);

    // 1: setup (zero cnt/off, W2 hi/lo, out=blin)
    setup_kernel<<<Nn / 256, 256>>>(W2, blin, out);
    // 2: histogram of dest rows
    hist_kernel<<<(E / 4 + 255) / 256, 256>>>(arow, E);
    // 3: W1 transpose+fp16 (coalesced)
    transpose_w1<<<Nn / 32, 256>>>(W1);
    // 4: GEMM1 (ncu capture target)
    gemm_hmma<0><<<Nn / 64, 256, 2 * 18432>>>(x, Nn);
    // 5: scan
    scan_kernel<<<1, 256>>>();
    // 6: scatter -> CSR
    scatter_kernel<<<(E + 255) / 256, 256>>>(arow, acol, aval, E);
    // 7: spmm layer1 + bias + relu
    spmm64_l1<<<(Nn * 32) / 256, 256>>>(b1);
    // 8: GEMM2 (split fp16, exact-ish)
    gemm_hmma<1><<<Nn / 64, 256, 2 * 36864>>>(nullptr, NH);
    // 9: spmm layer2 + bias + relu + gemm3 fused
    spmm64_l2<<<(Nn * 32) / 256, 256>>>(b2, W3);
    // 10: spmm layer3 + bias + log_softmax + linear head
    final_fused<<<Nn / 256, 256>>>(b3, Wlin, out);
}

// round 4
// speedup vs baseline: 1.4997x; 1.3788x over previous
#include <cuda_runtime.h>
#include <cuda_fp16.h>
#include <cstdint>
#include <math.h>

#define Nn 8192
#define NH 64
#define NC 8
#define MAXE (Nn * 32)

// ------------------------- device scratch (static, no allocs) ----------------
__device__ float g_S1[Nn * NH];
__device__ float g_H1[Nn * NH];
__device__ float g_S2[Nn * NH];
__device__ float g_S3[Nn * NC];
__device__ __half g_W1T_hi[NH * Nn];
__device__ __half g_W2T_hi[NH * NH];
__device__ __half g_W2T_lo[NH * NH];
__device__ int   g_cnt[Nn];
__device__ int   g_off[Nn];
__device__ int   g_rowptr[Nn + 1];
__device__ int   g_cols[MAXE];
__device__ float g_vals[MAXE];

#define LD32(p) (*reinterpret_cast<const uint32_t*>(p))
#define SWZ(o)  ((o) ^ (((o) >> 3) & 0x70))

// ------------------------- HMMA / async helpers ------------------------------
__device__ __forceinline__ void mma16816(float c[4], const uint32_t a[4],
                                         uint32_t b0, uint32_t b1) {
    asm volatile(
        "mma.sync.aligned.m16n8k16.row.col.f32.f16.f16.f32 "
        "{%0,%1,%2,%3}, {%4,%5,%6,%7}, {%8,%9}, {%0,%1,%2,%3};"
        : "+f"(c[0]), "+f"(c[1]), "+f"(c[2]), "+f"(c[3])
        : "r"(a[0]), "r"(a[1]), "r"(a[2]), "r"(a[3]), "r"(b0), "r"(b1));
}

__device__ __forceinline__ void cp_async16(void* dst, const void* src) {
    uint32_t d = (uint32_t)__cvta_generic_to_shared(dst);
    asm volatile("cp.async.cg.shared.global [%0], [%1], 16;" :: "r"(d), "l"(src));
}
__device__ __forceinline__ void cp_commit() {
    asm volatile("cp.async.commit_group;");
}
template <int N>
__device__ __forceinline__ void cp_wait() {
    asm volatile("cp.async.wait_group %0;" :: "n"(N));
}

__device__ __forceinline__ uint32_t pack_h2(float x, float y) {
    __half2 h = __floats2half2_rn(x, y);
    return *reinterpret_cast<uint32_t*>(&h);
}

// ------------------------- setup: zero cnt/off, W2 split, out init -----------
__global__ void setup_kernel(const float* __restrict__ W2,
                             const float* __restrict__ blin, float* __restrict__ out) {
    int i = blockIdx.x * blockDim.x + threadIdx.x;
    if (i < Nn) { g_cnt[i] = 0; g_off[i] = 0; }
    if (i < NH * NH) {
        int n = i >> 6, k = i & 63;
        float w = W2[k * NH + n];
        __half h = __float2half_rn(w);
        g_W2T_hi[i] = h;
        g_W2T_lo[i] = __float2half_rn(w - __half2float(h));
    }
    if (i < NC) out[i] = blin[0];
}

// ------------------------- hist (vectorized) ---------------------------------
__global__ void hist_kernel(const int* __restrict__ row, int E) {
    int i = (blockIdx.x * blockDim.x + threadIdx.x) * 4;
    if (i + 3 < E) {
        int4 r = *reinterpret_cast<const int4*>(row + i);
        atomicAdd(&g_cnt[r.x], 1);
        atomicAdd(&g_cnt[r.y], 1);
        atomicAdd(&g_cnt[r.z], 1);
        atomicAdd(&g_cnt[r.w], 1);
    } else {
        for (int j = i; j < E; j++) atomicAdd(&g_cnt[row[j]], 1);
    }
}

// ------------------------- W1 transpose (coalesced, smem tile) ---------------
__global__ void transpose_w1(const float* __restrict__ W1) {
    __shared__ float t[32][65];
    int k0 = blockIdx.x * 32;
    int tid = threadIdx.x;
    #pragma unroll
    for (int i = 0; i < 8; i++) {
        int j = tid + i * 256;
        int r = j >> 6, c = j & 63;
        t[r][c] = W1[(size_t)(k0 + r) * NH + c];
    }
    __syncthreads();
    #pragma unroll
    for (int i = 0; i < 8; i++) {
        int j = tid + i * 256;
        int c = j >> 5, r = j & 31;
        g_W1T_hi[(size_t)c * Nn + k0 + r] = __float2half_rn(t[r][c]);
    }
}

// ------------------------- shfl-based exclusive scan -------------------------
__global__ void scan_kernel() {
    __shared__ int wsum[8];
    int t = threadIdx.x, lane = t & 31, w = t >> 5;
    int base = t * 32;
    int s = 0;
    #pragma unroll
    for (int i = 0; i < 32; i++) s += g_cnt[base + i];
    int incl = s;
    #pragma unroll
    for (int o = 1; o < 32; o <<= 1) {
        int v = __shfl_up_sync(0xFFFFFFFFu, incl, o);
        if (lane >= o) incl += v;
    }
    if (lane == 31) wsum[w] = incl;
    __syncthreads();
    if (w == 0 && lane < 8) {
        int v = wsum[lane];
        int iw = v;
        #pragma unroll
        for (int o = 1; o < 8; o <<= 1) {
            int u = __shfl_up_sync(0x000000FFu, iw, o);
            if (lane >= o) iw += u;
        }
        wsum[lane] = iw - v;
    }
    __syncthreads();
    int acc = incl - s + wsum[w];
    #pragma unroll
    for (int i = 0; i < 32; i++) { g_rowptr[base + i] = acc; acc += g_cnt[base + i]; }
    if (t == 255) g_rowptr[Nn] = acc;
}

__global__ void scatter_kernel(const int* __restrict__ row, const int* __restrict__ col,
                               const float* __restrict__ val, int E) {
    int e = blockIdx.x * blockDim.x + threadIdx.x;
    if (e < E) {
        int r = row[e];
        int p = g_rowptr[r] + atomicAdd(&g_off[r], 1);
        g_cols[p] = col[e];
        g_vals[p] = val[e];
    }
}

// ------------------------- HMMA GEMM, cp.async-pipelined ---------------------
// C[8192 x 64] = A[8192 x Kdim] @ W[Kdim x 64]
// A kept fp32 in smem (SW128-swizzled 64x64 tile, 16KB), converted to fp16 at
// fragment-read time. B pre-converted fp16 (144B padded rows).
// MODE 0: B = W1T_hi only (1 product), 4-stage pipeline, nch = 128.
// MODE 1: A hi + residual on the fly, B hi/lo (3 products), nch = 1.
// 256 threads, 8 warps 4(m) x 2(n); block tile 64m x 64n.
template <int MODE>
__global__ void __launch_bounds__(256, 1)
gemm_hmma(const float* __restrict__ Aext, int Kdim) {
    constexpr int BOFF   = 16384;                       // A fp32 tile bytes
    constexpr int SLAB   = BOFF + (MODE ? 18432 : 9216);
    constexpr int STAGES = MODE ? 1 : 4;
    extern __shared__ char smem[];
    const int tid = threadIdx.x, lane = tid & 31, w = tid >> 5;
    const int m0 = blockIdx.x * 64;
    const int wm = (w & 3) * 16, wn = (w >> 2) * 32;
    const int g = lane >> 2, tg = lane & 3;

    const float* A = (MODE == 0) ? Aext : g_H1;
    const __half* BTh = (MODE == 0) ? g_W1T_hi : g_W2T_hi;
    const __half* BTl = (MODE == 0) ? (const __half*)nullptr : g_W2T_lo;
    float* C = (MODE == 0) ? g_S1 : g_S2;

    float acc[4][4];
    #pragma unroll
    for (int nt = 0; nt < 4; nt++)
        #pragma unroll
        for (int q = 0; q < 4; q++) acc[nt][q] = 0.f;

    const int nch = Kdim >> 6;

    auto issue = [&](int kc) {
        char* base = smem + (kc % STAGES) * SLAB;
        // A: 64 rows x 256B, 1024 16B units, 4 per thread, swizzled dst
        const float* Ab = A + (size_t)m0 * Kdim + (size_t)kc * 64;
        #pragma unroll
        for (int i = 0; i < 4; i++) {
            int j = tid + i * 256, r = j >> 4, c16 = j & 15;
            uint32_t off = r * 256 + c16 * 16;
            cp_async16(base + SWZ(off), Ab + (size_t)r * Kdim + c16 * 4);
        }
        // B: 64 rows x 128B, 512 units, 2 per thread
        #pragma unroll
        for (int i = 0; i < 2; i++) {
            int j = tid + i * 256, r = j >> 3, c = j & 7;
            cp_async16(base + BOFF + r * 144 + c * 16,
                       BTh + (size_t)r * Kdim + kc * 64 + c * 8);
            if (MODE == 1)
                cp_async16(base + BOFF + 9216 + r * 144 + c * 16,
                           BTl + (size_t)r * Kdim + kc * 64 + c * 8);
        }
    };

    auto compute = [&](const char* base) {
        const __half* Bh = (const __half*)(base + BOFF);
        const __half* Bl = (const __half*)(base + BOFF + 9216);
        #pragma unroll
        for (int ks = 0; ks < 4; ks++) {
            uint32_t ah[4], al[4];
            #pragma unroll
            for (int i = 0; i < 4; i++) {
                int row = wm + g + (i & 1) * 8;
                int colb = ks * 64 + tg * 8 + (i >> 1) * 32;   // byte col of fp32 pair
                uint32_t off = row * 256 + colb;
                float2 v = *reinterpret_cast<const float2*>(base + SWZ(off));
                ah[i] = pack_h2(v.x, v.y);
                if (MODE == 1) {
                    __half2 h = *reinterpret_cast<__half2*>(&ah[i]);
                    al[i] = pack_h2(v.x - __low2float(h), v.y - __high2float(h));
                }
            }
            // mma layout wants a[0]=r, a[1]=r+8, a[2]=c+8, a[3]=r+8,c+8:
            // our i encoding: i0=(r,c), i1=(r+8,c), i2=(r,c+8), i3=(r+8,c+8) — matches.
            #pragma unroll
            for (int nt = 0; nt < 4; nt++) {
                const __half* q = Bh + (wn + nt * 8 + g) * 72 + ks * 16 + 2 * tg;
                uint32_t b0 = LD32(q), b1 = LD32(q + 8);
                mma16816(acc[nt], ah, b0, b1);
                if (MODE == 1) {
                    const __half* ql = Bl + (wn + nt * 8 + g) * 72 + ks * 16 + 2 * tg;
                    uint32_t c0 = LD32(ql), c1 = LD32(ql + 8);
                    mma16816(acc[nt], ah, c0, c1);
                    mma16816(acc[nt], al, b0, b1);
                }
            }
        }
    };

    // prologue
    constexpr int PRE = MODE ? 1 : 3;
    #pragma unroll
    for (int s = 0; s < PRE; s++) {
        if (s < nch) issue(s);
        cp_commit();
    }
    for (int kc = 0; kc < nch; kc++) {
        cp_wait<MODE ? 0 : 2>();
        __syncthreads();               // buf kc ready; prev compute done
        if (kc + PRE < nch) issue(kc + PRE);
        cp_commit();
        compute(smem + (kc % STAGES) * SLAB);
    }

    #pragma unroll
    for (int nt = 0; nt < 4; nt++) {
        int row = m0 + wm + g;
        int col = wn + nt * 8 + 2 * tg;
        *reinterpret_cast<float2*>(&C[(size_t)row * 64 + col]) =
            make_float2(acc[nt][0], acc[nt][1]);
        *reinterpret_cast<float2*>(&C[(size_t)(row + 8) * 64 + col]) =
            make_float2(acc[nt][2], acc[nt][3]);
    }
}

// ------------------------- SpMM layer 1: S1 -> H1 (bias+relu) ---------------
__global__ void spmm64_l1(const float* __restrict__ bias) {
    int gt = blockIdx.x * blockDim.x + threadIdx.x;
    int row = gt >> 5, lane = gt & 31;
    if (row >= Nn) return;
    int s = g_rowptr[row], e = g_rowptr[row + 1];
    float a0 = 0.f, a1 = 0.f;
    #pragma unroll 4
    for (int i = s; i < e; i++) {
        int c = g_cols[i];
        float v = g_vals[i];
        const float* Sr = g_S1 + (size_t)c * 64;
        a0 += v * Sr[lane];
        a1 += v * Sr[lane + 32];
    }
    g_H1[(size_t)row * 64 + lane]      = fmaxf(a0 + bias[lane], 0.f);
    g_H1[(size_t)row * 64 + lane + 32] = fmaxf(a1 + bias[lane + 32], 0.f);
}

// ------------------------- SpMM layer 2 fused with gemm3: S2 -> S3 ----------
__global__ void spmm64_l2(const float* __restrict__ bias, const float* __restrict__ W3) {
    __shared__ float w3[NH * NC];
    int tid = threadIdx.x;
    for (int i = tid; i < NH * NC; i += blockDim.x) w3[i] = W3[i];
    __syncthreads();
    int gt = blockIdx.x * blockDim.x + tid;
    int row = gt >> 5, lane = gt & 31;
    if (row >= Nn) return;
    int s = g_rowptr[row], e = g_rowptr[row + 1];
    float a0 = 0.f, a1 = 0.f;
    #pragma unroll 4
    for (int i = s; i < e; i++) {
        int c = g_cols[i];
        float v = g_vals[i];
        const float* Sr = g_S2 + (size_t)c * 64;
        a0 += v * Sr[lane];
        a1 += v * Sr[lane + 32];
    }
    float r0 = fmaxf(a0 + bias[lane], 0.f);
    float r1 = fmaxf(a1 + bias[lane + 32], 0.f);
    float p[NC];
    #pragma unroll
    for (int f = 0; f < NC; f++)
        p[f] = r0 * w3[lane * NC + f] + r1 * w3[(lane + 32) * NC + f];
    #pragma unroll
    for (int o = 16; o > 0; o >>= 1)
        #pragma unroll
        for (int f = 0; f < NC; f++) p[f] += __shfl_xor_sync(0xFFFFFFFFu, p[f], o);
    if (lane == 0) {
        float* o8 = g_S3 + (size_t)row * NC;
        *reinterpret_cast<float4*>(o8)     = make_float4(p[0], p[1], p[2], p[3]);
        *reinterpret_cast<float4*>(o8 + 4) = make_float4(p[4], p[5], p[6], p[7]);
    }
}

// ------------------------- final: spmm8 + bias + log_softmax + head ---------
__global__ void final_fused(const float* __restrict__ b3, const float* __restrict__ Wlin,
                            float* __restrict__ out) {
    __shared__ float red[256 * NC];
    int t = threadIdx.x;
    int row = blockIdx.x * blockDim.x + t;
    float h[NC];
    {
        int s = g_rowptr[row], e = g_rowptr[row + 1];
        float a0 = 0.f, a1 = 0.f, a2 = 0.f, a3 = 0.f, a4 = 0.f, a5 = 0.f, a6 = 0.f, a7 = 0.f;
        #pragma unroll 2
        for (int i = s; i < e; i++) {
            int c = g_cols[i];
            float v = g_vals[i];
            const float4* p = reinterpret_cast<const float4*>(g_S3 + (size_t)c * NC);
            float4 q0 = p[0], q1 = p[1];
            a0 += v * q0.x; a1 += v * q0.y; a2 += v * q0.z; a3 += v * q0.w;
            a4 += v * q1.x; a5 += v * q1.y; a6 += v * q1.z; a7 += v * q1.w;
        }
        h[0] = a0 + b3[0]; h[1] = a1 + b3[1]; h[2] = a2 + b3[2]; h[3] = a3 + b3[3];
        h[4] = a4 + b3[4]; h[5] = a5 + b3[5]; h[6] = a6 + b3[6]; h[7] = a7 + b3[7];
    }
    float m = h[0];
    #pragma unroll
    for (int f = 1; f < NC; f++) m = fmaxf(m, h[f]);
    float ssum = 0.f;
    #pragma unroll
    for (int f = 0; f < NC; f++) ssum += expf(h[f] - m);
    float lse = m + logf(ssum);
    float wv = Wlin[row];
    #pragma unroll
    for (int f = 0; f < NC; f++) red[t * NC + f] = (h[f] - lse) * wv;
    __syncthreads();
    for (int s2 = 128; s2 > 0; s2 >>= 1) {
        if (t < s2) {
            #pragma unroll
            for (int f = 0; f < NC; f++) red[t * NC + f] += red[(t + s2) * NC + f];
        }
        __syncthreads();
    }
    if (t < NC) atomicAdd(&out[t], red[t]);
}

// ------------------------- launch -------------------------------------------
extern "C" void kernel_launch(void* const* d_in, const int* in_sizes, int n_in,
                              void* d_out, int out_size) {
    const float* x    = (const float*)d_in[0];
    const int*   arow = (const int*)d_in[1];
    const int*   acol = (const int*)d_in[2];
    const float* aval = (const float*)d_in[3];
    const float* W1   = (const float*)d_in[4];
    const float* b1   = (const float*)d_in[5];
    const float* W2   = (const float*)d_in[6];
    const float* b2   = (const float*)d_in[7];
    const float* W3   = (const float*)d_in[8];
    const float* b3   = (const float*)d_in[9];
    const float* Wlin = (const float*)d_in[10];
    const float* blin = (const float*)d_in[11];
    const int E = in_sizes[1];
    float* out = (float*)d_out;

    const int smem0 = 4 * (16384 + 9216);    // 102400
    const int smem1 = 1 * (16384 + 18432);   // 34816
    cudaFuncSetAttribute(gemm_hmma<0>, cudaFuncAttributeMaxDynamicSharedMemorySize, smem0);
    cudaFuncSetAttribute(gemm_hmma<1>, cudaFuncAttributeMaxDynamicSharedMemorySize, smem1);

    // 1: setup (zero cnt/off, W2 hi/lo, out=blin)
    setup_kernel<<<Nn / 256, 256>>>(W2, blin, out);
    // 2: histogram of dest rows
    hist_kernel<<<(E / 4 + 255) / 256, 256>>>(arow, E);
    // 3: W1 transpose+fp16 (coalesced)
    transpose_w1<<<Nn / 32, 256>>>(W1);
    // 4: GEMM1 (ncu capture target)
    gemm_hmma<0><<<Nn / 64, 256, smem0>>>(x, Nn);
    // 5: scan
    scan_kernel<<<1, 256>>>();
    // 6: scatter -> CSR
    scatter_kernel<<<(E + 255) / 256, 256>>>(arow, acol, aval, E);
    // 7: spmm layer1 + bias + relu
    spmm64_l1<<<(Nn * 32) / 256, 256>>>(b1);
    // 8: GEMM2 (split fp16)
    gemm_hmma<1><<<Nn / 64, 256, smem1>>>(nullptr, NH);
    // 9: spmm layer2 + bias + relu + gemm3 fused
    spmm64_l2<<<(Nn * 32) / 256, 256>>>(b2, W3);
    // 10: spmm layer3 + bias + log_softmax + linear head
    final_fused<<<Nn / 256, 256>>>(b3, Wlin, out);
}

// round 5
// speedup vs baseline: 1.5660x; 1.0442x over previous
#include <cuda_runtime.h>
#include <cuda_fp16.h>
#include <cstdint>
#include <math.h>

#define Nn 8192
#define NH 64
#define NC 8
#define MAXE (Nn * 32)

// ------------------------- device scratch (static, no allocs) ----------------
__device__ float g_S1[Nn * NH];
__device__ float g_H1[Nn * NH];
__device__ float g_S2[Nn * NH];
__device__ float g_S3[Nn * NC];
__device__ __half g_W1T_hi[NH * Nn];
__device__ __half g_W2T_hi[NH * NH];
__device__ __half g_W2T_lo[NH * NH];
__device__ int   g_cnt[Nn];
__device__ int   g_off[Nn];
__device__ int   g_rowptr[Nn + 1];
__device__ int   g_cols[MAXE];
__device__ float g_vals[MAXE];

#define LD32(p) (*reinterpret_cast<const uint32_t*>(p))
#define SWZ(o)  ((o) ^ (((o) >> 3) & 0x70))

// ------------------------- HMMA / async helpers ------------------------------
__device__ __forceinline__ void mma16816(float c[4], const uint32_t a[4],
                                         uint32_t b0, uint32_t b1) {
    asm volatile(
        "mma.sync.aligned.m16n8k16.row.col.f32.f16.f16.f32 "
        "{%0,%1,%2,%3}, {%4,%5,%6,%7}, {%8,%9}, {%0,%1,%2,%3};"
        : "+f"(c[0]), "+f"(c[1]), "+f"(c[2]), "+f"(c[3])
        : "r"(a[0]), "r"(a[1]), "r"(a[2]), "r"(a[3]), "r"(b0), "r"(b1));
}

__device__ __forceinline__ void cp_async16(void* dst, const void* src) {
    uint32_t d = (uint32_t)__cvta_generic_to_shared(dst);
    asm volatile("cp.async.cg.shared.global [%0], [%1], 16;" :: "r"(d), "l"(src));
}
__device__ __forceinline__ void cp_commit() {
    asm volatile("cp.async.commit_group;");
}
template <int N>
__device__ __forceinline__ void cp_wait() {
    asm volatile("cp.async.wait_group %0;" :: "n"(N));
}

__device__ __forceinline__ uint32_t pack_h2(float x, float y) {
    __half2 h = __floats2half2_rn(x, y);
    return *reinterpret_cast<uint32_t*>(&h);
}

// ------------------------- setup: zero S1/cnt/off, W2 split, out init --------
__global__ void setup_kernel(const float* __restrict__ W2,
                             const float* __restrict__ blin, float* __restrict__ out) {
    int i = blockIdx.x * blockDim.x + threadIdx.x;     // 0 .. 131071
    // zero g_S1 via float4 (131072 * 4 floats = Nn*NH)
    reinterpret_cast<float4*>(g_S1)[i] = make_float4(0.f, 0.f, 0.f, 0.f);
    if (i < Nn) { g_cnt[i] = 0; g_off[i] = 0; }
    if (i < NH * NH) {
        int n = i >> 6, k = i & 63;
        float w = W2[k * NH + n];
        __half h = __float2half_rn(w);
        g_W2T_hi[i] = h;
        g_W2T_lo[i] = __float2half_rn(w - __half2float(h));
    }
    if (i < NC) out[i] = blin[0];
}

// ------------------------- hist (vectorized) ---------------------------------
__global__ void hist_kernel(const int* __restrict__ row, int E) {
    int i = (blockIdx.x * blockDim.x + threadIdx.x) * 4;
    if (i + 3 < E) {
        int4 r = *reinterpret_cast<const int4*>(row + i);
        atomicAdd(&g_cnt[r.x], 1);
        atomicAdd(&g_cnt[r.y], 1);
        atomicAdd(&g_cnt[r.z], 1);
        atomicAdd(&g_cnt[r.w], 1);
    } else {
        for (int j = i; j < E; j++) atomicAdd(&g_cnt[row[j]], 1);
    }
}

// ------------------------- W1 transpose (coalesced, smem tile) ---------------
__global__ void transpose_w1(const float* __restrict__ W1) {
    __shared__ float t[32][65];
    int k0 = blockIdx.x * 32;
    int tid = threadIdx.x;
    #pragma unroll
    for (int i = 0; i < 8; i++) {
        int j = tid + i * 256;
        int r = j >> 6, c = j & 63;
        t[r][c] = W1[(size_t)(k0 + r) * NH + c];
    }
    __syncthreads();
    #pragma unroll
    for (int i = 0; i < 8; i++) {
        int j = tid + i * 256;
        int c = j >> 5, r = j & 31;
        g_W1T_hi[(size_t)c * Nn + k0 + r] = __float2half_rn(t[r][c]);
    }
}

// ------------------------- shfl-based exclusive scan -------------------------
__global__ void scan_kernel() {
    __shared__ int wsum[8];
    int t = threadIdx.x, lane = t & 31, w = t >> 5;
    int base = t * 32;
    int s = 0;
    #pragma unroll
    for (int i = 0; i < 32; i++) s += g_cnt[base + i];
    int incl = s;
    #pragma unroll
    for (int o = 1; o < 32; o <<= 1) {
        int v = __shfl_up_sync(0xFFFFFFFFu, incl, o);
        if (lane >= o) incl += v;
    }
    if (lane == 31) wsum[w] = incl;
    __syncthreads();
    if (w == 0 && lane < 8) {
        int v = wsum[lane];
        int iw = v;
        #pragma unroll
        for (int o = 1; o < 8; o <<= 1) {
            int u = __shfl_up_sync(0x000000FFu, iw, o);
            if (lane >= o) iw += u;
        }
        wsum[lane] = iw - v;
    }
    __syncthreads();
    int acc = incl - s + wsum[w];
    #pragma unroll
    for (int i = 0; i < 32; i++) { g_rowptr[base + i] = acc; acc += g_cnt[base + i]; }
    if (t == 255) g_rowptr[Nn] = acc;
}

__global__ void scatter_kernel(const int* __restrict__ row, const int* __restrict__ col,
                               const float* __restrict__ val, int E) {
    int e = blockIdx.x * blockDim.x + threadIdx.x;
    if (e < E) {
        int r = row[e];
        int p = g_rowptr[r] + atomicAdd(&g_off[r], 1);
        g_cols[p] = col[e];
        g_vals[p] = val[e];
    }
}

// ------------------------- HMMA GEMM, cp.async-pipelined ---------------------
// C[8192 x 64] = A[8192 x Kdim] @ W[Kdim x 64]
// MODE 0: K split across 2 CTAs (grid 256, 2 CTAs/SM); each does 64 chunks and
//         atomicAdds its partial tile into g_S1 (exactly 2 addends/elem ->
//         deterministic). B = W1T_hi only (1 product), 4-stage pipeline.
// MODE 1: A = g_H1 hi + on-the-fly residual, B = W2T hi/lo (3 products), 1 chunk.
// 256 threads, 8 warps 4(m) x 2(n); block tile 64m x 64n.
template <int MODE>
__global__ void __launch_bounds__(256, 2)
gemm_hmma(const float* __restrict__ Aext, int Kdim) {
    constexpr int BOFF   = 16384;                       // A fp32 tile bytes
    constexpr int SLAB   = BOFF + (MODE ? 18432 : 9216);
    constexpr int STAGES = MODE ? 1 : 4;
    extern __shared__ char smem[];
    const int tid = threadIdx.x, lane = tid & 31, w = tid >> 5;
    const int m0   = (MODE == 0) ? (blockIdx.x >> 1) * 64 : blockIdx.x * 64;
    const int koff = (MODE == 0) ? (blockIdx.x & 1) * 64 : 0;   // chunk offset
    const int wm = (w & 3) * 16, wn = (w >> 2) * 32;
    const int g = lane >> 2, tg = lane & 3;

    const float* A = (MODE == 0) ? Aext : g_H1;
    const __half* BTh = (MODE == 0) ? g_W1T_hi : g_W2T_hi;
    const __half* BTl = (MODE == 0) ? (const __half*)nullptr : g_W2T_lo;
    float* C = (MODE == 0) ? g_S1 : g_S2;

    float acc[4][4];
    #pragma unroll
    for (int nt = 0; nt < 4; nt++)
        #pragma unroll
        for (int q = 0; q < 4; q++) acc[nt][q] = 0.f;

    const int nch = (MODE == 0) ? (Kdim >> 7) : (Kdim >> 6);   // 64 : 1

    // hoisted loop-invariant fragment offsets
    uint32_t aoff[16];     // [ks*4 + i], swizzled byte offsets into A tile
    #pragma unroll
    for (int ks = 0; ks < 4; ks++)
        #pragma unroll
        for (int i = 0; i < 4; i++) {
            uint32_t o = (uint32_t)((wm + g + (i & 1) * 8) * 256 +
                                    ks * 64 + tg * 8 + (i >> 1) * 32);
            aoff[ks * 4 + i] = SWZ(o);
        }
    uint32_t boff[4];      // B row base per nt (byte offset into B tile)
    #pragma unroll
    for (int nt = 0; nt < 4; nt++)
        boff[nt] = (uint32_t)((wn + nt * 8 + g) * 144 + tg * 4);

    auto issue = [&](int kc) {
        char* base = smem + (kc % STAGES) * SLAB;
        const float* Ab = A + (size_t)m0 * Kdim + (size_t)(kc + koff) * 64;
        #pragma unroll
        for (int i = 0; i < 4; i++) {
            int j = tid + i * 256, r = j >> 4, c16 = j & 15;
            uint32_t off = r * 256 + c16 * 16;
            cp_async16(base + SWZ(off), Ab + (size_t)r * Kdim + c16 * 4);
        }
        #pragma unroll
        for (int i = 0; i < 2; i++) {
            int j = tid + i * 256, r = j >> 3, c = j & 7;
            cp_async16(base + BOFF + r * 144 + c * 16,
                       BTh + (size_t)r * Kdim + (kc + koff) * 64 + c * 8);
            if (MODE == 1)
                cp_async16(base + BOFF + 9216 + r * 144 + c * 16,
                           BTl + (size_t)r * Kdim + (kc + koff) * 64 + c * 8);
        }
    };

    auto compute = [&](const char* base) {
        #pragma unroll
        for (int ks = 0; ks < 4; ks++) {
            uint32_t ah[4], al[4];
            #pragma unroll
            for (int i = 0; i < 4; i++) {
                float2 v = *reinterpret_cast<const float2*>(base + aoff[ks * 4 + i]);
                ah[i] = pack_h2(v.x, v.y);
                if (MODE == 1) {
                    __half2 h = *reinterpret_cast<__half2*>(&ah[i]);
                    al[i] = pack_h2(v.x - __low2float(h), v.y - __high2float(h));
                }
            }
            #pragma unroll
            for (int nt = 0; nt < 4; nt++) {
                const char* q = base + BOFF + boff[nt] + ks * 32;
                uint32_t b0 = LD32(q), b1 = LD32(q + 16);
                mma16816(acc[nt], ah, b0, b1);
                if (MODE == 1) {
                    const char* ql = q + 9216;
                    uint32_t c0 = LD32(ql), c1 = LD32(ql + 16);
                    mma16816(acc[nt], ah, c0, c1);
                    mma16816(acc[nt], al, b0, b1);
                }
            }
        }
    };

    constexpr int PRE = MODE ? 1 : 3;
    #pragma unroll
    for (int s = 0; s < PRE; s++) {
        if (s < nch) issue(s);
        cp_commit();
    }
    for (int kc = 0; kc < nch; kc++) {
        cp_wait<MODE ? 0 : 2>();
        __syncthreads();
        if (kc + PRE < nch) issue(kc + PRE);
        cp_commit();
        compute(smem + (kc % STAGES) * SLAB);
    }

    #pragma unroll
    for (int nt = 0; nt < 4; nt++) {
        int row = m0 + wm + g;
        int col = wn + nt * 8 + 2 * tg;
        if (MODE == 0) {
            atomicAdd(&C[(size_t)row * 64 + col],       acc[nt][0]);
            atomicAdd(&C[(size_t)row * 64 + col + 1],   acc[nt][1]);
            atomicAdd(&C[(size_t)(row + 8) * 64 + col],     acc[nt][2]);
            atomicAdd(&C[(size_t)(row + 8) * 64 + col + 1], acc[nt][3]);
        } else {
            *reinterpret_cast<float2*>(&C[(size_t)row * 64 + col]) =
                make_float2(acc[nt][0], acc[nt][1]);
            *reinterpret_cast<float2*>(&C[(size_t)(row + 8) * 64 + col]) =
                make_float2(acc[nt][2], acc[nt][3]);
        }
    }
}

// ------------------------- SpMM layer 1: S1 -> H1 (bias+relu) ---------------
__global__ void spmm64_l1(const float* __restrict__ bias) {
    int gt = blockIdx.x * blockDim.x + threadIdx.x;
    int row = gt >> 5, lane = gt & 31;
    if (row >= Nn) return;
    int s = g_rowptr[row], e = g_rowptr[row + 1];
    float a0 = 0.f, a1 = 0.f;
    #pragma unroll 4
    for (int i = s; i < e; i++) {
        int c = g_cols[i];
        float v = g_vals[i];
        const float* Sr = g_S1 + (size_t)c * 64;
        a0 += v * Sr[lane];
        a1 += v * Sr[lane + 32];
    }
    g_H1[(size_t)row * 64 + lane]      = fmaxf(a0 + bias[lane], 0.f);
    g_H1[(size_t)row * 64 + lane + 32] = fmaxf(a1 + bias[lane + 32], 0.f);
}

// ------------------------- SpMM layer 2 fused with gemm3: S2 -> S3 ----------
__global__ void spmm64_l2(const float* __restrict__ bias, const float* __restrict__ W3) {
    __shared__ float w3[NH * NC];
    int tid = threadIdx.x;
    for (int i = tid; i < NH * NC; i += blockDim.x) w3[i] = W3[i];
    __syncthreads();
    int gt = blockIdx.x * blockDim.x + tid;
    int row = gt >> 5, lane = gt & 31;
    if (row >= Nn) return;
    int s = g_rowptr[row], e = g_rowptr[row + 1];
    float a0 = 0.f, a1 = 0.f;
    #pragma unroll 4
    for (int i = s; i < e; i++) {
        int c = g_cols[i];
        float v = g_vals[i];
        const float* Sr = g_S2 + (size_t)c * 64;
        a0 += v * Sr[lane];
        a1 += v * Sr[lane + 32];
    }
    float r0 = fmaxf(a0 + bias[lane], 0.f);
    float r1 = fmaxf(a1 + bias[lane + 32], 0.f);
    float p[NC];
    #pragma unroll
    for (int f = 0; f < NC; f++)
        p[f] = r0 * w3[lane * NC + f] + r1 * w3[(lane + 32) * NC + f];
    #pragma unroll
    for (int o = 16; o > 0; o >>= 1)
        #pragma unroll
        for (int f = 0; f < NC; f++) p[f] += __shfl_xor_sync(0xFFFFFFFFu, p[f], o);
    if (lane == 0) {
        float* o8 = g_S3 + (size_t)row * NC;
        *reinterpret_cast<float4*>(o8)     = make_float4(p[0], p[1], p[2], p[3]);
        *reinterpret_cast<float4*>(o8 + 4) = make_float4(p[4], p[5], p[6], p[7]);
    }
}

// ------------------------- final: spmm8 + bias + log_softmax + head ---------
__global__ void final_fused(const float* __restrict__ b3, const float* __restrict__ Wlin,
                            float* __restrict__ out) {
    __shared__ float red[256 * NC];
    int t = threadIdx.x;
    int row = blockIdx.x * blockDim.x + t;
    float h[NC];
    {
        int s = g_rowptr[row], e = g_rowptr[row + 1];
        float a0 = 0.f, a1 = 0.f, a2 = 0.f, a3 = 0.f, a4 = 0.f, a5 = 0.f, a6 = 0.f, a7 = 0.f;
        #pragma unroll 2
        for (int i = s; i < e; i++) {
            int c = g_cols[i];
            float v = g_vals[i];
            const float4* p = reinterpret_cast<const float4*>(g_S3 + (size_t)c * NC);
            float4 q0 = p[0], q1 = p[1];
            a0 += v * q0.x; a1 += v * q0.y; a2 += v * q0.z; a3 += v * q0.w;
            a4 += v * q1.x; a5 += v * q1.y; a6 += v * q1.z; a7 += v * q1.w;
        }
        h[0] = a0 + b3[0]; h[1] = a1 + b3[1]; h[2] = a2 + b3[2]; h[3] = a3 + b3[3];
        h[4] = a4 + b3[4]; h[5] = a5 + b3[5]; h[6] = a6 + b3[6]; h[7] = a7 + b3[7];
    }
    float m = h[0];
    #pragma unroll
    for (int f = 1; f < NC; f++) m = fmaxf(m, h[f]);
    float ssum = 0.f;
    #pragma unroll
    for (int f = 0; f < NC; f++) ssum += expf(h[f] - m);
    float lse = m + logf(ssum);
    float wv = Wlin[row];
    #pragma unroll
    for (int f = 0; f < NC; f++) red[t * NC + f] = (h[f] - lse) * wv;
    __syncthreads();
    for (int s2 = 128; s2 > 0; s2 >>= 1) {
        if (t < s2) {
            #pragma unroll
            for (int f = 0; f < NC; f++) red[t * NC + f] += red[(t + s2) * NC + f];
        }
        __syncthreads();
    }
    if (t < NC) atomicAdd(&out[t], red[t]);
}

// ------------------------- launch -------------------------------------------
extern "C" void kernel_launch(void* const* d_in, const int* in_sizes, int n_in,
                              void* d_out, int out_size) {
    const float* x    = (const float*)d_in[0];
    const int*   arow = (const int*)d_in[1];
    const int*   acol = (const int*)d_in[2];
    const float* aval = (const float*)d_in[3];
    const float* W1   = (const float*)d_in[4];
    const float* b1   = (const float*)d_in[5];
    const float* W2   = (const float*)d_in[6];
    const float* b2   = (const float*)d_in[7];
    const float* W3   = (const float*)d_in[8];
    const float* b3   = (const float*)d_in[9];
    const float* Wlin = (const float*)d_in[10];
    const float* blin = (const float*)d_in[11];
    const int E = in_sizes[1];
    float* out = (float*)d_out;

    const int smem0 = 4 * (16384 + 9216);    // 102400 (x2 CTAs = 204.8KB/SM)
    const int smem1 = 1 * (16384 + 18432);   // 34816
    cudaFuncSetAttribute(gemm_hmma<0>, cudaFuncAttributeMaxDynamicSharedMemorySize, smem0);
    cudaFuncSetAttribute(gemm_hmma<1>, cudaFuncAttributeMaxDynamicSharedMemorySize, smem1);

    // 1: setup (zero S1/cnt/off, W2 hi/lo, out=blin)
    setup_kernel<<<512, 256>>>(W2, blin, out);
    // 2: histogram of dest rows
    hist_kernel<<<(E / 4 + 255) / 256, 256>>>(arow, E);
    // 3: W1 transpose+fp16 (coalesced)
    transpose_w1<<<Nn / 32, 256>>>(W1);
    // 4: GEMM1, K-split x2 (ncu capture target)
    gemm_hmma<0><<<2 * Nn / 64, 256, smem0>>>(x, Nn);
    // 5: scan
    scan_kernel<<<1, 256>>>();
    // 6: scatter -> CSR
    scatter_kernel<<<(E + 255) / 256, 256>>>(arow, acol, aval, E);
    // 7: spmm layer1 + bias + relu
    spmm64_l1<<<(Nn * 32) / 256, 256>>>(b1);
    // 8: GEMM2 (split fp16)
    gemm_hmma<1><<<Nn / 64, 256, smem1>>>(nullptr, NH);
    // 9: spmm layer2 + bias + relu + gemm3 fused
    spmm64_l2<<<(Nn * 32) / 256, 256>>>(b2, W3);
    // 10: spmm layer3 + bias + log_softmax + linear head
    final_fused<<<Nn / 256, 256>>>(b3, Wlin, out);
}

// round 6
// speedup vs baseline: 1.5834x; 1.0111x over previous
#include <cuda_runtime.h>
#include <cuda_fp16.h>
#include <cstdint>
#include <math.h>

#define Nn 8192
#define NH 64
#define NC 8
#define MAXE (Nn * 32)

// ------------------------- device scratch (static, no allocs) ----------------
__device__ float g_S1[Nn * NH];
__device__ float g_H1[Nn * NH];
__device__ float g_S2[Nn * NH];
__device__ float g_S3[Nn * NC];
__device__ __half g_W1T_hi[NH * Nn];
__device__ __half g_W2T_hi[NH * NH];
__device__ __half g_W2T_lo[NH * NH];
__device__ int   g_cnt[Nn];
__device__ int   g_off[Nn];
__device__ int   g_rowptr[Nn + 1];
__device__ int   g_cols[MAXE];
__device__ float g_vals[MAXE];

#define LD32(p) (*reinterpret_cast<const uint32_t*>(p))
#define SWZ(o)  ((o) ^ (((o) >> 3) & 0x70))

// ------------------------- HMMA / async helpers ------------------------------
__device__ __forceinline__ void mma16816(float c[4], const uint32_t a[4],
                                         uint32_t b0, uint32_t b1) {
    asm volatile(
        "mma.sync.aligned.m16n8k16.row.col.f32.f16.f16.f32 "
        "{%0,%1,%2,%3}, {%4,%5,%6,%7}, {%8,%9}, {%0,%1,%2,%3};"
        : "+f"(c[0]), "+f"(c[1]), "+f"(c[2]), "+f"(c[3])
        : "r"(a[0]), "r"(a[1]), "r"(a[2]), "r"(a[3]), "r"(b0), "r"(b1));
}

__device__ __forceinline__ void cp_async16(void* dst, const void* src) {
    uint32_t d = (uint32_t)__cvta_generic_to_shared(dst);
    asm volatile("cp.async.cg.shared.global [%0], [%1], 16;" :: "r"(d), "l"(src));
}
__device__ __forceinline__ void cp_commit() {
    asm volatile("cp.async.commit_group;");
}
template <int N>
__device__ __forceinline__ void cp_wait() {
    asm volatile("cp.async.wait_group %0;" :: "n"(N));
}

__device__ __forceinline__ uint32_t pack_h2(float x, float y) {
    __half2 h = __floats2half2_rn(x, y);
    return *reinterpret_cast<uint32_t*>(&h);
}

// ------------------------- setup: zero S1/cnt/off, W2 split, out init --------
__global__ void setup_kernel(const float* __restrict__ W2,
                             const float* __restrict__ blin, float* __restrict__ out) {
    int i = blockIdx.x * blockDim.x + threadIdx.x;     // 0 .. 131071
    reinterpret_cast<float4*>(g_S1)[i] = make_float4(0.f, 0.f, 0.f, 0.f);
    if (i < Nn) { g_cnt[i] = 0; g_off[i] = 0; }
    if (i < NH * NH) {
        int n = i >> 6, k = i & 63;
        float w = W2[k * NH + n];
        __half h = __float2half_rn(w);
        g_W2T_hi[i] = h;
        g_W2T_lo[i] = __float2half_rn(w - __half2float(h));
    }
    if (i < NC) out[i] = blin[0];
}

// ------------------------- hist (vectorized, 8/thread) -----------------------
__global__ void hist_kernel(const int* __restrict__ row, int E) {
    int i = (blockIdx.x * blockDim.x + threadIdx.x) * 8;
    if (i + 7 < E) {
        int4 r0 = *reinterpret_cast<const int4*>(row + i);
        int4 r1 = *reinterpret_cast<const int4*>(row + i + 4);
        atomicAdd(&g_cnt[r0.x], 1); atomicAdd(&g_cnt[r0.y], 1);
        atomicAdd(&g_cnt[r0.z], 1); atomicAdd(&g_cnt[r0.w], 1);
        atomicAdd(&g_cnt[r1.x], 1); atomicAdd(&g_cnt[r1.y], 1);
        atomicAdd(&g_cnt[r1.z], 1); atomicAdd(&g_cnt[r1.w], 1);
    } else {
        for (int j = i; j < E; j++) atomicAdd(&g_cnt[row[j]], 1);
    }
}

// ------------------------- W1 transpose (coalesced, smem tile) ---------------
__global__ void transpose_w1(const float* __restrict__ W1) {
    __shared__ float t[32][65];
    int k0 = blockIdx.x * 32;
    int tid = threadIdx.x;
    #pragma unroll
    for (int i = 0; i < 8; i++) {
        int j = tid + i * 256;
        int r = j >> 6, c = j & 63;
        t[r][c] = W1[(size_t)(k0 + r) * NH + c];
    }
    __syncthreads();
    #pragma unroll
    for (int i = 0; i < 8; i++) {
        int j = tid + i * 256;
        int c = j >> 5, r = j & 31;
        g_W1T_hi[(size_t)c * Nn + k0 + r] = __float2half_rn(t[r][c]);
    }
}

// ------------------------- shfl-based exclusive scan -------------------------
__global__ void scan_kernel() {
    __shared__ int wsum[8];
    int t = threadIdx.x, lane = t & 31, w = t >> 5;
    int base = t * 32;
    int s = 0;
    #pragma unroll
    for (int i = 0; i < 32; i++) s += g_cnt[base + i];
    int incl = s;
    #pragma unroll
    for (int o = 1; o < 32; o <<= 1) {
        int v = __shfl_up_sync(0xFFFFFFFFu, incl, o);
        if (lane >= o) incl += v;
    }
    if (lane == 31) wsum[w] = incl;
    __syncthreads();
    if (w == 0 && lane < 8) {
        int v = wsum[lane];
        int iw = v;
        #pragma unroll
        for (int o = 1; o < 8; o <<= 1) {
            int u = __shfl_up_sync(0x000000FFu, iw, o);
            if (lane >= o) iw += u;
        }
        wsum[lane] = iw - v;
    }
    __syncthreads();
    int acc = incl - s + wsum[w];
    #pragma unroll
    for (int i = 0; i < 32; i++) { g_rowptr[base + i] = acc; acc += g_cnt[base + i]; }
    if (t == 255) g_rowptr[Nn] = acc;
}

__global__ void scatter_kernel(const int* __restrict__ row, const int* __restrict__ col,
                               const float* __restrict__ val, int E) {
    int e = blockIdx.x * blockDim.x + threadIdx.x;
    if (e < E) {
        int r = row[e];
        int p = g_rowptr[r] + atomicAdd(&g_off[r], 1);
        g_cols[p] = col[e];
        g_vals[p] = val[e];
    }
}

// ------------------------- HMMA GEMM, cp.async-pipelined ---------------------
// MODE 0: S1 = x @ W1.  K split x4 (grid 512, 2 CTAs/SM, ~3.5 waves for
//         balance). Stage = 2 K64 chunks (K128), 2 stages, 1 barrier/stage.
//         All cp.async src ptrs / swizzled dst offsets hoisted to registers.
//         Epilogue: atomicAdd into zeroed g_S1 (4 addends/elem).
// MODE 1: S2 = H1 @ W2, K=64 single chunk, fp16 hi/lo x hi/lo (3 products).
// 256 threads, 8 warps 4(m) x 2(n); block tile 64m x 64n.
template <int MODE>
__global__ void __launch_bounds__(256, 2)
gemm_hmma(const float* __restrict__ Aext, int Kdim) {
    extern __shared__ char smem[];
    const int tid = threadIdx.x, lane = tid & 31, w = tid >> 5;
    const int wm = (w & 3) * 16, wn = (w >> 2) * 32;
    const int g = lane >> 2, tg = lane & 3;

    float acc[4][4];
    #pragma unroll
    for (int nt = 0; nt < 4; nt++)
        #pragma unroll
        for (int q = 0; q < 4; q++) acc[nt][q] = 0.f;

    // loop-invariant fragment offsets (per K64 sub-tile)
    uint32_t aoff[16];
    #pragma unroll
    for (int ks = 0; ks < 4; ks++)
        #pragma unroll
        for (int i = 0; i < 4; i++) {
            uint32_t o = (uint32_t)((wm + g + (i & 1) * 8) * 256 +
                                    ks * 64 + tg * 8 + (i >> 1) * 32);
            aoff[ks * 4 + i] = SWZ(o);
        }
    uint32_t boff[4];
    #pragma unroll
    for (int nt = 0; nt < 4; nt++)
        boff[nt] = (uint32_t)((wn + nt * 8 + g) * 144 + tg * 4);

    if (MODE == 0) {
        const int m0 = (blockIdx.x >> 2) * 64;
        const int kq = blockIdx.x & 3;           // K quarter: 32 chunks = 16 stages
        // stage layout: A0@0 A1@16384 B0@32768 B1@41984 ; stage stride 51200
        const float* asrc[8]; uint32_t adst[8];
        #pragma unroll
        for (int i = 0; i < 8; i++) {
            int ch = i >> 2, ii = i & 3, j = tid + ii * 256, r = j >> 4, c = j & 15;
            asrc[i] = Aext + (size_t)(m0 + r) * Kdim + kq * 2048 + ch * 64 + c * 4;
            adst[i] = ch * 16384 + SWZ((uint32_t)(r * 256 + c * 16));
        }
        const __half* bsrc[4]; uint32_t bdst[4];
        #pragma unroll
        for (int i = 0; i < 4; i++) {
            int ch = i >> 1, ii = i & 1, j = tid + ii * 256, r = j >> 3, c = j & 7;
            bsrc[i] = g_W1T_hi + (size_t)r * Kdim + kq * 2048 + ch * 64 + c * 8;
            bdst[i] = 32768u + ch * 9216 + r * 144 + c * 16;
        }
        auto issue = [&](char* base) {
            #pragma unroll
            for (int i = 0; i < 8; i++) { cp_async16(base + adst[i], asrc[i]); asrc[i] += 128; }
            #pragma unroll
            for (int i = 0; i < 4; i++) { cp_async16(base + bdst[i], bsrc[i]); bsrc[i] += 128; }
            cp_commit();
        };

        issue(smem);
        #pragma unroll 1
        for (int kp = 0; kp < 16; kp++) {
            cp_wait<0>();
            __syncthreads();
            if (kp + 1 < 16) issue(smem + ((kp + 1) & 1) * 51200);
            const char* base = smem + (kp & 1) * 51200;
            #pragma unroll
            for (int ch = 0; ch < 2; ch++) {
                const char* ab = base + ch * 16384;
                const char* bb = base + 32768 + ch * 9216;
                #pragma unroll
                for (int ks = 0; ks < 4; ks++) {
                    uint32_t ah[4];
                    #pragma unroll
                    for (int i = 0; i < 4; i++) {
                        float2 v = *reinterpret_cast<const float2*>(ab + aoff[ks * 4 + i]);
                        ah[i] = pack_h2(v.x, v.y);
                    }
                    #pragma unroll
                    for (int nt = 0; nt < 4; nt++) {
                        const char* q = bb + boff[nt] - 32768 + ks * 32 + 32768;
                        mma16816(acc[nt], ah, LD32(q), LD32(q + 16));
                    }
                }
            }
        }
        #pragma unroll
        for (int nt = 0; nt < 4; nt++) {
            int row = m0 + wm + g;
            int col = wn + nt * 8 + 2 * tg;
            atomicAdd(&g_S1[(size_t)row * 64 + col],           acc[nt][0]);
            atomicAdd(&g_S1[(size_t)row * 64 + col + 1],       acc[nt][1]);
            atomicAdd(&g_S1[(size_t)(row + 8) * 64 + col],     acc[nt][2]);
            atomicAdd(&g_S1[(size_t)(row + 8) * 64 + col + 1], acc[nt][3]);
        }
    } else {
        // -------- MODE 1: one K=64 chunk, A=H1 (residual on the fly), B hi/lo
        const int m0 = blockIdx.x * 64;
        // layout: A fp32 @0 (16KB), Bh @16384 (9216), Bl @25600 (9216)
        #pragma unroll
        for (int i = 0; i < 4; i++) {
            int j = tid + i * 256, r = j >> 4, c = j & 15;
            cp_async16(smem + SWZ((uint32_t)(r * 256 + c * 16)),
                       g_H1 + (size_t)(m0 + r) * 64 + c * 4);
        }
        #pragma unroll
        for (int i = 0; i < 2; i++) {
            int j = tid + i * 256, r = j >> 3, c = j & 7;
            cp_async16(smem + 16384 + r * 144 + c * 16, g_W2T_hi + (size_t)r * 64 + c * 8);
            cp_async16(smem + 25600 + r * 144 + c * 16, g_W2T_lo + (size_t)r * 64 + c * 8);
        }
        cp_commit();
        cp_wait<0>();
        __syncthreads();
        #pragma unroll
        for (int ks = 0; ks < 4; ks++) {
            uint32_t ah[4], al[4];
            #pragma unroll
            for (int i = 0; i < 4; i++) {
                float2 v = *reinterpret_cast<const float2*>(smem + aoff[ks * 4 + i]);
                ah[i] = pack_h2(v.x, v.y);
                __half2 h = *reinterpret_cast<__half2*>(&ah[i]);
                al[i] = pack_h2(v.x - __low2float(h), v.y - __high2float(h));
            }
            #pragma unroll
            for (int nt = 0; nt < 4; nt++) {
                const char* q  = smem + 16384 + boff[nt] + ks * 32;
                const char* ql = q + 9216;
                uint32_t b0 = LD32(q),  b1 = LD32(q + 16);
                uint32_t c0 = LD32(ql), c1 = LD32(ql + 16);
                mma16816(acc[nt], ah, b0, b1);
                mma16816(acc[nt], ah, c0, c1);
                mma16816(acc[nt], al, b0, b1);
            }
        }
        #pragma unroll
        for (int nt = 0; nt < 4; nt++) {
            int row = m0 + wm + g;
            int col = wn + nt * 8 + 2 * tg;
            *reinterpret_cast<float2*>(&g_S2[(size_t)row * 64 + col]) =
                make_float2(acc[nt][0], acc[nt][1]);
            *reinterpret_cast<float2*>(&g_S2[(size_t)(row + 8) * 64 + col]) =
                make_float2(acc[nt][2], acc[nt][3]);
        }
    }
}

// ------------------------- SpMM layer 1: S1 -> H1 (bias+relu) ---------------
__global__ void spmm64_l1(const float* __restrict__ bias) {
    int gt = blockIdx.x * blockDim.x + threadIdx.x;
    int row = gt >> 5, lane = gt & 31;
    if (row >= Nn) return;
    int s = g_rowptr[row], e = g_rowptr[row + 1];
    float a0 = 0.f, a1 = 0.f;
    #pragma unroll 4
    for (int i = s; i < e; i++) {
        int c = g_cols[i];
        float v = g_vals[i];
        const float* Sr = g_S1 + (size_t)c * 64;
        a0 += v * Sr[lane];
        a1 += v * Sr[lane + 32];
    }
    g_H1[(size_t)row * 64 + lane]      = fmaxf(a0 + bias[lane], 0.f);
    g_H1[(size_t)row * 64 + lane + 32] = fmaxf(a1 + bias[lane + 32], 0.f);
}

// ------------------------- SpMM layer 2 fused with gemm3: S2 -> S3 ----------
__global__ void spmm64_l2(const float* __restrict__ bias, const float* __restrict__ W3) {
    __shared__ float w3[NH * NC];
    int tid = threadIdx.x;
    for (int i = tid; i < NH * NC; i += blockDim.x) w3[i] = W3[i];
    __syncthreads();
    int gt = blockIdx.x * blockDim.x + tid;
    int row = gt >> 5, lane = gt & 31;
    if (row >= Nn) return;
    int s = g_rowptr[row], e = g_rowptr[row + 1];
    float a0 = 0.f, a1 = 0.f;
    #pragma unroll 4
    for (int i = s; i < e; i++) {
        int c = g_cols[i];
        float v = g_vals[i];
        const float* Sr = g_S2 + (size_t)c * 64;
        a0 += v * Sr[lane];
        a1 += v * Sr[lane + 32];
    }
    float r0 = fmaxf(a0 + bias[lane], 0.f);
    float r1 = fmaxf(a1 + bias[lane + 32], 0.f);
    float p[NC];
    #pragma unroll
    for (int f = 0; f < NC; f++)
        p[f] = r0 * w3[lane * NC + f] + r1 * w3[(lane + 32) * NC + f];
    #pragma unroll
    for (int o = 16; o > 0; o >>= 1)
        #pragma unroll
        for (int f = 0; f < NC; f++) p[f] += __shfl_xor_sync(0xFFFFFFFFu, p[f], o);
    if (lane == 0) {
        float* o8 = g_S3 + (size_t)row * NC;
        *reinterpret_cast<float4*>(o8)     = make_float4(p[0], p[1], p[2], p[3]);
        *reinterpret_cast<float4*>(o8 + 4) = make_float4(p[4], p[5], p[6], p[7]);
    }
}

// ------------------------- final: spmm8 + bias + log_softmax + head ---------
__global__ void final_fused(const float* __restrict__ b3, const float* __restrict__ Wlin,
                            float* __restrict__ out) {
    __shared__ float red[256 * NC];
    int t = threadIdx.x;
    int row = blockIdx.x * blockDim.x + t;
    float h[NC];
    {
        int s = g_rowptr[row], e = g_rowptr[row + 1];
        float a0 = 0.f, a1 = 0.f, a2 = 0.f, a3 = 0.f, a4 = 0.f, a5 = 0.f, a6 = 0.f, a7 = 0.f;
        #pragma unroll 2
        for (int i = s; i < e; i++) {
            int c = g_cols[i];
            float v = g_vals[i];
            const float4* p = reinterpret_cast<const float4*>(g_S3 + (size_t)c * NC);
            float4 q0 = p[0], q1 = p[1];
            a0 += v * q0.x; a1 += v * q0.y; a2 += v * q0.z; a3 += v * q0.w;
            a4 += v * q1.x; a5 += v * q1.y; a6 += v * q1.z; a7 += v * q1.w;
        }
        h[0] = a0 + b3[0]; h[1] = a1 + b3[1]; h[2] = a2 + b3[2]; h[3] = a3 + b3[3];
        h[4] = a4 + b3[4]; h[5] = a5 + b3[5]; h[6] = a6 + b3[6]; h[7] = a7 + b3[7];
    }
    float m = h[0];
    #pragma unroll
    for (int f = 1; f < NC; f++) m = fmaxf(m, h[f]);
    float ssum = 0.f;
    #pragma unroll
    for (int f = 0; f < NC; f++) ssum += expf(h[f] - m);
    float lse = m + logf(ssum);
    float wv = Wlin[row];
    #pragma unroll
    for (int f = 0; f < NC; f++) red[t * NC + f] = (h[f] - lse) * wv;
    __syncthreads();
    for (int s2 = 128; s2 > 0; s2 >>= 1) {
        if (t < s2) {
            #pragma unroll
            for (int f = 0; f < NC; f++) red[t * NC + f] += red[(t + s2) * NC + f];
        }
        __syncthreads();
    }
    if (t < NC) atomicAdd(&out[t], red[t]);
}

// ------------------------- launch -------------------------------------------
extern "C" void kernel_launch(void* const* d_in, const int* in_sizes, int n_in,
                              void* d_out, int out_size) {
    const float* x    = (const float*)d_in[0];
    const int*   arow = (const int*)d_in[1];
    const int*   acol = (const int*)d_in[2];
    const float* aval = (const float*)d_in[3];
    const float* W1   = (const float*)d_in[4];
    const float* b1   = (const float*)d_in[5];
    const float* W2   = (const float*)d_in[6];
    const float* b2   = (const float*)d_in[7];
    const float* W3   = (const float*)d_in[8];
    const float* b3   = (const float*)d_in[9];
    const float* Wlin = (const float*)d_in[10];
    const float* blin = (const float*)d_in[11];
    const int E = in_sizes[1];
    float* out = (float*)d_out;

    const int smem0 = 2 * 51200;             // 102400 (x2 CTAs = 204.8KB/SM)
    const int smem1 = 16384 + 2 * 9216;      // 34816
    cudaFuncSetAttribute(gemm_hmma<0>, cudaFuncAttributeMaxDynamicSharedMemorySize, smem0);
    cudaFuncSetAttribute(gemm_hmma<1>, cudaFuncAttributeMaxDynamicSharedMemorySize, smem1);

    // 1: setup (zero S1/cnt/off, W2 hi/lo, out=blin)
    setup_kernel<<<512, 256>>>(W2, blin, out);
    // 2: histogram of dest rows
    hist_kernel<<<(E / 8 + 255) / 256, 256>>>(arow, E);
    // 3: W1 transpose+fp16 (coalesced)
    transpose_w1<<<Nn / 32, 256>>>(W1);
    // 4: GEMM1, K-split x4 (ncu capture target)
    gemm_hmma<0><<<4 * Nn / 64, 256, smem0>>>(x, Nn);
    // 5: scan
    scan_kernel<<<1, 256>>>();
    // 6: scatter -> CSR
    scatter_kernel<<<(E + 255) / 256, 256>>>(arow, acol, aval, E);
    // 7: spmm layer1 + bias + relu
    spmm64_l1<<<(Nn * 32) / 256, 256>>>(b1);
    // 8: GEMM2 (split fp16)
    gemm_hmma<1><<<Nn / 64, 256, smem1>>>(nullptr, NH);
    // 9: spmm layer2 + bias + relu + gemm3 fused
    spmm64_l2<<<(Nn * 32) / 256, 256>>>(b2, W3);
    // 10: spmm layer3 + bias + log_softmax + linear head
    final_fused<<<Nn / 256, 256>>>(b3, Wlin, out);
}